// round 2
// baseline (speedup 1.0000x reference)
#include <cuda_runtime.h>
#include <math.h>

#define NB 4
#define CC 64
#define HH 64
#define WW 64
#define LL 4096      // H*W
#define FF 256       // masked feature dim: 4 offsets * 64 channels

// Output layout (flattened reference tuple, all float32):
//   S:          [0,       16384)
//   U:          [16384,   32768)
//   ref_unfold: [32768,   32768+9437184)
//   arg:        [9469952, 9486336)
#define OUT_S 0
#define OUT_U 16384
#define OUT_R 32768
#define OUT_A 9469952

// Scratch (static __device__ arrays — no allocation)
__device__ float g_Ut[NB][FF][LL];     // normalized masked features, k-major (16 MB)
__device__ float g_P[NB][HH][WW];      // per-pixel sum over channels of y^2
__device__ float g_rnorm[NB][LL];      // 1 / max(norm, 1e-12)
__device__ int   g_arg[NB][LL];

// Causal mask keeps patch offsets (i,j) in {(0,0),(0,1),(0,2),(1,0)}
// -> spatial offsets (dy,dx) relative to the pixel:
__device__ __constant__ int c_dy[4] = {-1, -1, -1, 0};
__device__ __constant__ int c_dx[4] = {-1,  0,  1, -1};

// ---------------------------------------------------------------------------
// Kernel 1a: per-pixel channel-sum of squares (coalesced over x)
__global__ void kP(const float* __restrict__ yhat) {
    int b = blockIdx.x;            // n*HH + y
    int n = b >> 6, y = b & 63;
    int x = threadIdx.x;           // 0..63
    const float* p = yhat + (((long)n * CC) * HH + y) * WW + x;
    float s = 0.f;
    #pragma unroll 8
    for (int c = 0; c < CC; ++c) {
        float v = p[(long)c * HH * WW];
        s += v * v;
    }
    g_P[n][y][x] = s;
}

// Kernel 1b: reciprocal norms per position
__global__ void kNorm() {
    int idx = blockIdx.x * blockDim.x + threadIdx.x;   // n*LL + l
    int n = idx >> 12, l = idx & 4095;
    int y = l >> 6, x = l & 63;
    float s = 0.f;
    #pragma unroll
    for (int o = 0; o < 4; ++o) {
        int yy = y + c_dy[o], xx = x + c_dx[o];
        if (yy >= 0 && xx >= 0 && xx < WW) s += g_P[n][yy][xx];
    }
    float nrm = fmaxf(sqrtf(s), 1e-12f);
    g_rnorm[n][l] = 1.0f / nrm;
}

// Kernel 1c: build normalized feature matrix, k-major [n][f][l] (coalesced in l)
__global__ void kBuild(const float* __restrict__ yhat) {
    int e = blockIdx.x * blockDim.x + threadIdx.x;     // < NB*FF*LL = 4M
    int l = e & 4095;
    int f = (e >> 12) & 255;
    int n = e >> 20;
    int y = l >> 6, x = l & 63;
    int off = f >> 6, c = f & 63;
    int yy = y + c_dy[off], xx = x + c_dx[off];
    float v = 0.f;
    if (yy >= 0 && xx >= 0 && xx < WW)
        v = yhat[(((long)n * CC + c) * HH + yy) * WW + xx];
    g_Ut[n][f][l] = v * g_rnorm[n][l];
}

// ---------------------------------------------------------------------------
// Kernel 2: triangular max-argmax GEMM.
// Block handles one (batch n, m-tile of 64) and scans ALL l-tiles <= mt.
// 256 threads, 4x4 microtile, k-major smem tiles with stride-68 padding.
__global__ void __launch_bounds__(256) kGemm(const float* __restrict__ yprob,
                                             float* __restrict__ out) {
    __shared__ float sA[64][68];   // [k][l]
    __shared__ float sB[64][68];   // [k][m]
    __shared__ float rv[64][17];
    __shared__ int   rl[64][17];

    int bx  = blockIdx.x;          // 0..255
    int idx = bx >> 2;             // 0..63
    int n   = bx & 3;
    int mt  = 63 - idx;            // big work first
    int m0  = mt << 6;

    const float* __restrict__ Ut = &g_Ut[n][0][0];    // [256][4096]

    int tid  = threadIdx.x;
    int tx   = tid & 15;           // m group
    int ty   = tid >> 4;           // l group
    int lrow = tid >> 4;           // load row base 0..15
    int lc4  = tid & 15;           // float4 column 0..15

    float bestv[4];
    int   bestl[4];
    #pragma unroll
    for (int j = 0; j < 4; ++j) { bestv[j] = -INFINITY; bestl[j] = 0x7fffffff; }

    for (int lt = 0; lt <= mt; ++lt) {
        int l0 = lt << 6;
        float acc[4][4];
        #pragma unroll
        for (int i = 0; i < 4; ++i)
            #pragma unroll
            for (int j = 0; j < 4; ++j) acc[i][j] = 0.f;

        for (int kc = 0; kc < 4; ++kc) {
            int k0 = kc << 6;
            __syncthreads();
            #pragma unroll
            for (int q = 0; q < 4; ++q) {
                int r = lrow + (q << 4);
                const float4 va = *(const float4*)&Ut[(long)(k0 + r) * LL + l0 + (lc4 << 2)];
                const float4 vb = *(const float4*)&Ut[(long)(k0 + r) * LL + m0 + (lc4 << 2)];
                *(float4*)&sA[r][lc4 << 2] = va;
                *(float4*)&sB[r][lc4 << 2] = vb;
            }
            __syncthreads();
            #pragma unroll 16
            for (int k = 0; k < 64; ++k) {
                float4 a = *(const float4*)&sA[k][ty << 2];
                float4 b = *(const float4*)&sB[k][tx << 2];
                float av[4] = {a.x, a.y, a.z, a.w};
                float bw[4] = {b.x, b.y, b.z, b.w};
                #pragma unroll
                for (int i = 0; i < 4; ++i)
                    #pragma unroll
                    for (int j = 0; j < 4; ++j)
                        acc[i][j] = fmaf(av[i], bw[j], acc[i][j]);
            }
        }

        // fold this tile into the running per-thread best (causal l < m)
        int lbase = l0 + (ty << 2);
        int mbase = m0 + (tx << 2);
        #pragma unroll
        for (int j = 0; j < 4; ++j) {
            int m = mbase + j;
            #pragma unroll
            for (int i = 0; i < 4; ++i) {
                int l = lbase + i;
                float v = acc[i][j];
                if (l < m && (v > bestv[j] || (v == bestv[j] && l < bestl[j]))) {
                    bestv[j] = v; bestl[j] = l;
                }
            }
        }
    }

    // cross-thread (ty) reduction per m column, tie-break = smallest l
    #pragma unroll
    for (int j = 0; j < 4; ++j) {
        rv[(tx << 2) + j][ty] = bestv[j];
        rl[(tx << 2) + j][ty] = bestl[j];
    }
    __syncthreads();

    if (tid < 64) {
        float bv = rv[tid][0];
        int   bl = rl[tid][0];
        #pragma unroll
        for (int t = 1; t < 16; ++t) {
            float v = rv[tid][t];
            int   l = rl[tid][t];
            if (v > bv || (v == bv && l < bl)) { bv = v; bl = l; }
        }
        int m = m0 + tid;
        float S, U, A;
        if (m == 0) {
            S = 1e-8f; U = 1e-8f; A = -1.f; bl = -1;
        } else {
            // reference max includes implicit zeros at l >= m
            if (bv < 0.f) { bv = 0.f; bl = m; }
            S = fminf(fmaxf(bv, 1e-8f), 1.0f);
            float up = yprob[n * LL + bl];
            U = fminf(fmaxf(up, 1e-8f), 1.0f);
            A = (float)bl;
        }
        g_arg[n][m] = bl;
        out[OUT_S + n * LL + m] = S;
        out[OUT_U + n * LL + m] = U;
        out[OUT_A + n * LL + m] = A;
    }
}

// ---------------------------------------------------------------------------
// Kernel 3: ref_unfold gather. Coalesced writes along m; y_hat planes cache-hit.
__global__ void kOut(const float* __restrict__ yhat, float* __restrict__ out) {
    long e = (long)blockIdx.x * blockDim.x + threadIdx.x;  // < NB*576*LL
    int m = (int)(e & 4095);
    int t = (int)(e >> 12);      // n*576 + f
    int f = t % 576;
    int n = t / 576;
    float v = 0.f;
    if (m != 0) {
        int a  = g_arg[n][m];
        int c  = f / 9, ij = f % 9;
        int i  = ij / 3, j = ij % 3;
        int ay = a >> 6, ax = a & 63;
        int yy = ay + i - 1, xx = ax + j - 1;
        if (yy >= 0 && yy < HH && xx >= 0 && xx < WW)
            v = yhat[(((long)n * CC + c) * HH + yy) * WW + xx];
    }
    out[OUT_R + e] = v;
}

// ---------------------------------------------------------------------------
extern "C" void kernel_launch(void* const* d_in, const int* in_sizes, int n_in,
                              void* d_out, int out_size) {
    const float* yhat  = (const float*)d_in[0];   // [4,64,64,64]
    const float* yprob = (const float*)d_in[1];   // [4,1,64,64]
    float* out = (float*)d_out;

    kP<<<NB * HH, WW>>>(yhat);
    kNorm<<<(NB * LL) / 256, 256>>>();
    kBuild<<<(NB * FF * LL) / 256, 256>>>(yhat);
    kGemm<<<256, 256>>>(yprob, out);
    kOut<<<(NB * 576 * LL) / 256, 256>>>(yhat, out);
}

// round 3
// speedup vs baseline: 2.2062x; 2.2062x over previous
#include <cuda_runtime.h>
#include <math.h>

#define NB 4
#define CC 64
#define HH 64
#define WW 64
#define LL 4096
#define FF 256

#define OUT_S 0
#define OUT_U 16384
#define OUT_R 32768
#define OUT_A 9469952

typedef unsigned long long ull;

__device__ float g_Ut[NB][FF][LL];     // normalized masked features, k-major
__device__ float g_P[NB][HH][WW];
__device__ float g_rnorm[NB][LL];
__device__ int   g_arg[NB][LL];
__device__ ull   g_best[NB][LL];       // packed (sortable(v)<<32) | ~l

__device__ __constant__ int c_dy[4] = {-1, -1, -1, 0};
__device__ __constant__ int c_dx[4] = {-1,  0,  1, -1};

// packed-f32x2 FMA: two fp32 FMAs per instruction, bit-identical per lane
#define FMA2(d, a, b) asm("fma.rn.f32x2 %0, %1, %2, %0;" : "+l"(d) : "l"(a), "l"(b))
#define DUP2(d, f)    asm("mov.b64 %0, {%1, %1};" : "=l"(d) : "r"(__float_as_uint(f)))

__device__ __forceinline__ unsigned sortable(float v) {
    unsigned u = __float_as_uint(v);
    return (u & 0x80000000u) ? ~u : (u | 0x80000000u);
}
__device__ __forceinline__ float unsortable(unsigned s) {
    unsigned u = (s & 0x80000000u) ? (s ^ 0x80000000u) : ~s;
    return __uint_as_float(u);
}

// ---------------------------------------------------------------------------
__global__ void kP(const float* __restrict__ yhat) {
    int b = blockIdx.x;
    int n = b >> 6, y = b & 63;
    int x = threadIdx.x;
    const float* p = yhat + (((long)n * CC) * HH + y) * WW + x;
    float s = 0.f;
    #pragma unroll 8
    for (int c = 0; c < CC; ++c) {
        float v = p[(long)c * HH * WW];
        s += v * v;
    }
    g_P[n][y][x] = s;
}

__global__ void kNorm() {
    int idx = blockIdx.x * blockDim.x + threadIdx.x;
    int n = idx >> 12, l = idx & 4095;
    int y = l >> 6, x = l & 63;
    float s = 0.f;
    #pragma unroll
    for (int o = 0; o < 4; ++o) {
        int yy = y + c_dy[o], xx = x + c_dx[o];
        if (yy >= 0 && xx >= 0 && xx < WW) s += g_P[n][yy][xx];
    }
    float nrm = fmaxf(sqrtf(s), 1e-12f);
    g_rnorm[n][l] = 1.0f / nrm;
    ((ull*)g_best)[idx] = 0ull;        // init packed-best sentinel
}

__global__ void kBuild(const float* __restrict__ yhat) {
    int e = blockIdx.x * blockDim.x + threadIdx.x;
    int l = e & 4095;
    int f = (e >> 12) & 255;
    int n = e >> 20;
    int y = l >> 6, x = l & 63;
    int off = f >> 6, c = f & 63;
    int yy = y + c_dy[off], xx = x + c_dx[off];
    float v = 0.f;
    if (yy >= 0 && xx >= 0 && xx < WW)
        v = yhat[(((long)n * CC + c) * HH + yy) * WW + xx];
    g_Ut[n][f][l] = v * g_rnorm[n][l];
}

// ---------------------------------------------------------------------------
// Triangular max-argmax GEMM. 128x128 tiles, 8x8 microtile (2x2 quadrants of 4),
// packed f32x2 FMAs. Block = (m-tile mt, chunk of 2 l-tiles). Partials merged
// via 64-bit packed atomicMax.
__global__ void __launch_bounds__(256) kGemm() {
    __shared__ __align__(16) float sm[8448];
    float* sA = sm;            // [32][132]
    float* sB = sm + 4224;     // [32][132]

    int n = blockIdx.y;
    int b = blockIdx.x;
    // decode flat chunk id: group g covers mt in [2g, 2g+1], each with g+1 chunks
    int g = 0;
    while ((g + 1) * (g + 2) <= b) ++g;
    int r  = b - g * (g + 1);
    int q_ = r / (g + 1);
    int mt = 2 * g + q_;
    int ch = r - q_ * (g + 1);
    int m0 = mt << 7;

    const float* __restrict__ Ut = &g_Ut[n][0][0];

    int tid = threadIdx.x;
    int tx  = tid & 15;        // m quadrant index
    int ty  = tid >> 4;        // l quadrant index
    int row = tid >> 3;        // load row 0..31
    int cb  = tid & 7;         // load float4 col base

    float bestv[8];
    int   bestl[8];
    #pragma unroll
    for (int j = 0; j < 8; ++j) { bestv[j] = -INFINITY; bestl[j] = 0x7fffffff; }

    #pragma unroll 1
    for (int t = 0; t < 2; ++t) {
        int lt = ch * 2 + t;
        if (lt > mt) break;
        int l0 = lt << 7;

        ull acc[4][8];
        #pragma unroll
        for (int i = 0; i < 4; ++i)
            #pragma unroll
            for (int j = 0; j < 8; ++j) acc[i][j] = 0ull;

        #pragma unroll 1
        for (int kc = 0; kc < 8; ++kc) {
            int k0 = kc << 5;
            __syncthreads();
            #pragma unroll
            for (int q = 0; q < 4; ++q) {
                int c4 = cb + (q << 3);               // float4 col 0..31
                const float* gr = Ut + (long)(k0 + row) * LL;
                *(float4*)&sA[row * 132 + (c4 << 2)] =
                    *(const float4*)&gr[l0 + (c4 << 2)];
                *(float4*)&sB[row * 132 + (c4 << 2)] =
                    *(const float4*)&gr[m0 + (c4 << 2)];
            }
            __syncthreads();

            #pragma unroll
            for (int k = 0; k < 32; ++k) {
                const float* ra = sA + k * 132;
                const float* rb = sB + k * 132;
                ulonglong2 A0 = *(const ulonglong2*)(ra + (ty << 2));
                ulonglong2 A1 = *(const ulonglong2*)(ra + 64 + (ty << 2));
                float4 B0 = *(const float4*)(rb + (tx << 2));
                float4 B1 = *(const float4*)(rb + 64 + (tx << 2));
                ull ap[4] = {A0.x, A0.y, A1.x, A1.y};
                float bf[8] = {B0.x, B0.y, B0.z, B0.w, B1.x, B1.y, B1.z, B1.w};
                #pragma unroll
                for (int j = 0; j < 8; ++j) {
                    ull bb;
                    DUP2(bb, bf[j]);
                    #pragma unroll
                    for (int i = 0; i < 4; ++i) FMA2(acc[i][j], ap[i], bb);
                }
            }
        }

        // fold tile into running best (causal l < m, first-occurrence ties)
        #pragma unroll
        for (int j = 0; j < 8; ++j) {
            int m = m0 + ((j < 4) ? (tx << 2) + j : 64 + (tx << 2) + (j - 4));
            #pragma unroll
            for (int p = 0; p < 4; ++p) {
                int lb = l0 + ((p < 2) ? (ty << 2) + p * 2
                                       : 64 + (ty << 2) + (p - 2) * 2);
                ull a = acc[p][j];
                float v0 = __uint_as_float((unsigned)(a & 0xffffffffu));
                float v1 = __uint_as_float((unsigned)(a >> 32));
                if (lb < m && (v0 > bestv[j] || (v0 == bestv[j] && lb < bestl[j]))) {
                    bestv[j] = v0; bestl[j] = lb;
                }
                int l1 = lb + 1;
                if (l1 < m && (v1 > bestv[j] || (v1 == bestv[j] && l1 < bestl[j]))) {
                    bestv[j] = v1; bestl[j] = l1;
                }
            }
        }
    }

    // cross-ty reduction in smem (reuse tile memory), then one atomic per m
    __syncthreads();
    float* rv = sm;                    // [128][16]
    int*   rl = (int*)(sm + 2048);     // [128][16]
    #pragma unroll
    for (int j = 0; j < 8; ++j) {
        int col = (j < 4) ? (tx << 2) + j : 64 + (tx << 2) + (j - 4);
        rv[col * 16 + ty] = bestv[j];
        rl[col * 16 + ty] = bestl[j];
    }
    __syncthreads();
    if (tid < 128) {
        float bv = rv[tid * 16];
        int   bl = rl[tid * 16];
        #pragma unroll
        for (int u = 1; u < 16; ++u) {
            float v = rv[tid * 16 + u];
            int   l = rl[tid * 16 + u];
            if (v > bv || (v == bv && l < bl)) { bv = v; bl = l; }
        }
        bv += 0.0f;                    // canonicalize -0.0 -> +0.0
        ull key = ((ull)sortable(bv) << 32) | (unsigned)(~bl);
        atomicMax(&g_best[n][m0 + tid], key);
    }
}

// ---------------------------------------------------------------------------
__global__ void kFinal(const float* __restrict__ yprob, float* __restrict__ out) {
    int idx = blockIdx.x * blockDim.x + threadIdx.x;   // n*LL + m
    int n = idx >> 12, m = idx & 4095;
    float S, U, A;
    int bl;
    if (m == 0) {
        S = 1e-8f; U = 1e-8f; A = -1.f; bl = -1;
    } else {
        ull key = g_best[n][m];
        float bv = unsortable((unsigned)(key >> 32));
        bl = (int)(~(unsigned)(key & 0xffffffffu));
        if (bv < 0.f) { bv = 0.f; bl = m; }            // safety (unreachable: l=0 gives 0.0)
        S = fminf(fmaxf(bv, 1e-8f), 1.0f);
        U = fminf(fmaxf(yprob[n * LL + bl], 1e-8f), 1.0f);
        A = (float)bl;
    }
    g_arg[n][m] = bl;
    out[OUT_S + idx] = S;
    out[OUT_U + idx] = U;
    out[OUT_A + idx] = A;
}

__global__ void kOut(const float* __restrict__ yhat, float* __restrict__ out) {
    long e = (long)blockIdx.x * blockDim.x + threadIdx.x;
    int m = (int)(e & 4095);
    int t = (int)(e >> 12);
    int f = t % 576;
    int n = t / 576;
    float v = 0.f;
    if (m != 0) {
        int a  = g_arg[n][m];
        int c  = f / 9, ij = f % 9;
        int i  = ij / 3, j = ij % 3;
        int ay = a >> 6, ax = a & 63;
        int yy = ay + i - 1, xx = ax + j - 1;
        if (yy >= 0 && yy < HH && xx >= 0 && xx < WW)
            v = yhat[(((long)n * CC + c) * HH + yy) * WW + xx];
    }
    out[OUT_R + e] = v;
}

// ---------------------------------------------------------------------------
extern "C" void kernel_launch(void* const* d_in, const int* in_sizes, int n_in,
                              void* d_out, int out_size) {
    const float* yhat  = (const float*)d_in[0];
    const float* yprob = (const float*)d_in[1];
    float* out = (float*)d_out;

    kP<<<NB * HH, WW>>>(yhat);
    kNorm<<<(NB * LL) / 256, 256>>>();
    kBuild<<<(NB * FF * LL) / 256, 256>>>(yhat);
    kGemm<<<dim3(272, NB), 256>>>();
    kFinal<<<(NB * LL) / 256, 256>>>(yprob, out);
    kOut<<<(NB * 576 * LL) / 256, 256>>>(yhat, out);
}

// round 5
// speedup vs baseline: 2.4738x; 1.1213x over previous
#include <cuda_runtime.h>
#include <math.h>

#define NB 4
#define CC 64
#define HH 64
#define WW 64
#define LL 4096
#define FF 256

#define OUT_S 0
#define OUT_U 16384
#define OUT_R 32768
#define OUT_A 9469952

typedef unsigned long long ull;

__device__ float g_Ut[NB][FF][LL];     // normalized masked features, k-major
__device__ float g_P[NB][HH][WW];
__device__ float g_rnorm[NB][LL];
__device__ int   g_arg[NB][LL];
__device__ ull   g_best[NB][LL];       // packed (sortable(v)<<32) | ~l

__device__ __constant__ int c_dy[4] = {-1, -1, -1, 0};
__device__ __constant__ int c_dx[4] = {-1,  0,  1, -1};

// packed-f32x2 FMA: two fp32 FMAs per instruction, bit-identical per lane
#define FMA2(d, a, b) asm("fma.rn.f32x2 %0, %1, %2, %0;" : "+l"(d) : "l"(a), "l"(b))
#define DUP2(d, f)    asm("mov.b64 %0, {%1, %1};" : "=l"(d) : "r"(__float_as_uint(f)))

#define CP16(dst, src) asm volatile( \
    "cp.async.cg.shared.global [%0], [%1], 16;" :: "r"(dst), "l"(src))
#define CP_COMMIT() asm volatile("cp.async.commit_group;")
#define CP_WAIT0()  asm volatile("cp.async.wait_group 0;")

__device__ __forceinline__ unsigned sortable(float v) {
    unsigned u = __float_as_uint(v);
    return (u & 0x80000000u) ? ~u : (u | 0x80000000u);
}
__device__ __forceinline__ float unsortable(unsigned s) {
    unsigned u = (s & 0x80000000u) ? (s ^ 0x80000000u) : ~s;
    return __uint_as_float(u);
}

// ---------------------------------------------------------------------------
__global__ void kP(const float* __restrict__ yhat) {
    int b = blockIdx.x;
    int n = b >> 6, y = b & 63;
    int x = threadIdx.x;
    const float* p = yhat + (((long)n * CC) * HH + y) * WW + x;
    float s = 0.f;
    #pragma unroll 8
    for (int c = 0; c < CC; ++c) {
        float v = p[(long)c * HH * WW];
        s += v * v;
    }
    g_P[n][y][x] = s;
}

__global__ void kNorm() {
    int idx = blockIdx.x * blockDim.x + threadIdx.x;
    int n = idx >> 12, l = idx & 4095;
    int y = l >> 6, x = l & 63;
    float s = 0.f;
    #pragma unroll
    for (int o = 0; o < 4; ++o) {
        int yy = y + c_dy[o], xx = x + c_dx[o];
        if (yy >= 0 && xx >= 0 && xx < WW) s += g_P[n][yy][xx];
    }
    float nrm = fmaxf(sqrtf(s), 1e-12f);
    g_rnorm[n][l] = 1.0f / nrm;
    ((ull*)g_best)[idx] = 0ull;        // reset packed-best each replay
}

__global__ void kBuild(const float* __restrict__ yhat) {
    int e = blockIdx.x * blockDim.x + threadIdx.x;
    int l = e & 4095;
    int f = (e >> 12) & 255;
    int n = e >> 20;
    int y = l >> 6, x = l & 63;
    int off = f >> 6, c = f & 63;
    int yy = y + c_dy[off], xx = x + c_dx[off];
    float v = 0.f;
    if (yy >= 0 && xx >= 0 && xx < WW)
        v = yhat[(((long)n * CC + c) * HH + yy) * WW + xx];
    g_Ut[n][f][l] = v * g_rnorm[n][l];
}

// ---------------------------------------------------------------------------
// Triangular max-argmax GEMM.
// One 128x128 l-tile x 256-k per block. Double-buffered cp.async pipeline,
// k-chunks of 16. 8x8 microtile via f32x2 packed FMAs. Warp footprint
// 4 tx-groups x 8 ty-groups (minimizes unique LDS bytes per warp-k).
__global__ void __launch_bounds__(256) kGemm() {
    // stage s: A [16][128] at s*4096, B [16][128] at s*4096 + 2048
    __shared__ __align__(16) float sm[8192];

    int n = blockIdx.y;
    int b = blockIdx.x;                 // 0..527: b = mt*(mt+1)/2 + lt
    int mt = (int)((sqrtf(8.f * b + 1.f) - 1.f) * 0.5f);
    while ((mt + 1) * (mt + 2) / 2 <= b) ++mt;
    while (mt * (mt + 1) / 2 > b) --mt;
    int lt = b - mt * (mt + 1) / 2;
    int m0 = mt << 7, l0 = lt << 7;

    const float* __restrict__ Ut = &g_Ut[n][0][0];

    int tid  = threadIdx.x;
    int w    = tid >> 5, lane = tid & 31;
    int tx   = ((w & 3) << 2) | (lane & 3);    // 0..15 (4 distinct per warp)
    int ty   = ((w >> 2) << 3) | (lane >> 2);  // 0..15 (8 distinct per warp)
    int row  = tid >> 4;                       // load row 0..15
    int c0   = tid & 15;                       // load float4 col base

    unsigned sbase = (unsigned)__cvta_generic_to_shared(sm);

    // prefetch chunk 0 into stage 0
    {
        const float* gr = Ut + (long)row * LL;
        #pragma unroll
        for (int q = 0; q < 2; ++q) {
            int c4 = c0 + (q << 4);
            CP16(sbase + ((row << 7) + (c4 << 2)) * 4, gr + l0 + (c4 << 2));
            CP16(sbase + (2048 + (row << 7) + (c4 << 2)) * 4, gr + m0 + (c4 << 2));
        }
        CP_COMMIT();
    }

    ull acc[4][8];
    #pragma unroll
    for (int i = 0; i < 4; ++i)
        #pragma unroll
        for (int j = 0; j < 8; ++j) acc[i][j] = 0ull;

    #pragma unroll 1
    for (int kc = 0; kc < 16; ++kc) {
        CP_WAIT0();
        __syncthreads();

        if (kc < 15) {                  // prefetch next chunk into other stage
            int k0 = (kc + 1) << 4;
            unsigned sdst = sbase + (((kc + 1) & 1) << 14);  // *4096 floats *4B
            const float* gr = Ut + (long)(k0 + row) * LL;
            #pragma unroll
            for (int q = 0; q < 2; ++q) {
                int c4 = c0 + (q << 4);
                CP16(sdst + ((row << 7) + (c4 << 2)) * 4, gr + l0 + (c4 << 2));
                CP16(sdst + (2048 + (row << 7) + (c4 << 2)) * 4, gr + m0 + (c4 << 2));
            }
            CP_COMMIT();
        }

        const float* buf = sm + ((kc & 1) << 12);
        #pragma unroll
        for (int k = 0; k < 16; ++k) {
            const float* ra = buf + (k << 7);
            const float* rb = ra + 2048;
            ulonglong2 A0 = *(const ulonglong2*)(ra + (ty << 2));
            ulonglong2 A1 = *(const ulonglong2*)(ra + 64 + (ty << 2));
            float4 B0 = *(const float4*)(rb + (tx << 2));
            float4 B1 = *(const float4*)(rb + 64 + (tx << 2));
            ull ap[4] = {A0.x, A0.y, A1.x, A1.y};
            float bf[8] = {B0.x, B0.y, B0.z, B0.w, B1.x, B1.y, B1.z, B1.w};
            #pragma unroll
            for (int j = 0; j < 8; ++j) {
                ull bb;
                DUP2(bb, bf[j]);
                #pragma unroll
                for (int i = 0; i < 4; ++i) FMA2(acc[i][j], ap[i], bb);
            }
        }
    }

    // fold into per-thread best (causal l < m, first-occurrence ties)
    float bestv[8];
    int   bestl[8];
    #pragma unroll
    for (int j = 0; j < 8; ++j) { bestv[j] = -INFINITY; bestl[j] = 0x7fffffff; }

    #pragma unroll
    for (int j = 0; j < 8; ++j) {
        int m = m0 + ((j < 4) ? (tx << 2) + j : 64 + (tx << 2) + (j - 4));
        #pragma unroll
        for (int p = 0; p < 4; ++p) {
            int lb = l0 + ((p < 2) ? (ty << 2) + p * 2
                                   : 64 + (ty << 2) + (p - 2) * 2);
            ull a = acc[p][j];
            float v0 = __uint_as_float((unsigned)(a & 0xffffffffu));
            float v1 = __uint_as_float((unsigned)(a >> 32));
            if (lb < m && (v0 > bestv[j] || (v0 == bestv[j] && lb < bestl[j]))) {
                bestv[j] = v0; bestl[j] = lb;
            }
            int l1 = lb + 1;
            if (l1 < m && (v1 > bestv[j] || (v1 == bestv[j] && l1 < bestl[j]))) {
                bestv[j] = v1; bestl[j] = l1;
            }
        }
    }

    // cross-ty reduction in smem, then one packed atomicMax per m-column
    __syncthreads();
    float* rv = sm;                    // [128][16]
    int*   rl = (int*)(sm + 2048);     // [128][16]
    #pragma unroll
    for (int j = 0; j < 8; ++j) {
        int col = (j < 4) ? (tx << 2) + j : 64 + (tx << 2) + (j - 4);
        rv[col * 16 + ty] = bestv[j];
        rl[col * 16 + ty] = bestl[j];
    }
    __syncthreads();
    if (tid < 128) {
        float bv = rv[tid * 16];
        int   bl = rl[tid * 16];
        #pragma unroll
        for (int u = 1; u < 16; ++u) {
            float v = rv[tid * 16 + u];
            int   l = rl[tid * 16 + u];
            if (v > bv || (v == bv && l < bl)) { bv = v; bl = l; }
        }
        bv += 0.0f;                    // canonicalize -0.0 -> +0.0
        ull key = ((ull)sortable(bv) << 32) | (unsigned)(~bl);
        atomicMax(&g_best[n][m0 + tid], key);
    }
}

// ---------------------------------------------------------------------------
__global__ void kFinal(const float* __restrict__ yprob, float* __restrict__ out) {
    int idx = blockIdx.x * blockDim.x + threadIdx.x;   // n*LL + m
    int n = idx >> 12, m = idx & 4095;
    float S, U, A;
    int bl;
    if (m == 0) {
        S = 1e-8f; U = 1e-8f; A = -1.f; bl = -1;
    } else {
        ull key = g_best[n][m];
        float bv = unsortable((unsigned)(key >> 32));
        bl = (int)(~(unsigned)(key & 0xffffffffu));
        if (bv < 0.f) { bv = 0.f; bl = m; }
        S = fminf(fmaxf(bv, 1e-8f), 1.0f);
        U = fminf(fmaxf(yprob[n * LL + bl], 1e-8f), 1.0f);
        A = (float)bl;
    }
    g_arg[n][m] = bl;
    out[OUT_S + idx] = S;
    out[OUT_U + idx] = U;
    out[OUT_A + idx] = A;
}

__global__ void kOut(const float* __restrict__ yhat, float* __restrict__ out) {
    long e = (long)blockIdx.x * blockDim.x + threadIdx.x;
    int m = (int)(e & 4095);
    int t = (int)(e >> 12);
    int f = t % 576;
    int n = t / 576;
    float v = 0.f;
    if (m != 0) {
        int a  = g_arg[n][m];
        int c  = f / 9, ij = f % 9;
        int i  = ij / 3, j = ij % 3;
        int ay = a >> 6, ax = a & 63;
        int yy = ay + i - 1, xx = ax + j - 1;
        if (yy >= 0 && yy < HH && xx >= 0 && xx < WW)
            v = yhat[(((long)n * CC + c) * HH + yy) * WW + xx];
    }
    out[OUT_R + e] = v;
}

// ---------------------------------------------------------------------------
extern "C" void kernel_launch(void* const* d_in, const int* in_sizes, int n_in,
                              void* d_out, int out_size) {
    const float* yhat  = (const float*)d_in[0];
    const float* yprob = (const float*)d_in[1];
    float* out = (float*)d_out;

    kP<<<NB * HH, WW>>>(yhat);
    kNorm<<<(NB * LL) / 256, 256>>>();
    kBuild<<<(NB * FF * LL) / 256, 256>>>(yhat);
    kGemm<<<dim3(528, NB), 256>>>();
    kFinal<<<(NB * LL) / 256, 256>>>(yprob, out);
    kOut<<<(NB * 576 * LL) / 256, 256>>>(yhat, out);
}